// round 11
// baseline (speedup 1.0000x reference)
#include <cuda_runtime.h>
#include <cstdint>
#include <math.h>

#define N_SEQ   16384
#define TBL_N   1024               // intervals; TBL_N+1 knots
#define CHUNK   4096               // elements per map block
#define NCHUNK  (N_SEQ / CHUNK)    // 4 chunks per row

// -------------------------- device scratch ---------------------------------
__device__ __align__(8)  float2 g_tbl2[TBL_N];    // (f[i], f[i+1]) pairs
__device__ __align__(16) float4 g_coef[TBL_N];    // (G_i, a_i, b_i, 0)
__device__ float2 g_range;                        // (lo, inv_h)
__device__ float  g_h;                            // knot spacing
// packed weights: pW[k4 * NROWS + row] = float4 of W[row][4*k4 .. 4*k4+3]
__device__ __align__(16) float4 g_pW2[8  * 64];
__device__ __align__(16) float4 g_pW3[16 * 64];
__device__ __align__(16) float4 g_pW4[16 * 32];

// -------------------------- math helpers -----------------------------------
__device__ __forceinline__ float splus(float x) {
    float e = __expf(-fabsf(x));
    return fmaxf(x, 0.0f) + __logf(1.0f + e);
}

// -------------------------- kernel 0: prep (1 block, 256 thr) ---------------
// (a) min/max from row edges (t sorted per row), (b) pack weights float4-
// transposed so table_kernel's loads are coalesced.
__global__ __launch_bounds__(256) void prep_kernel(
    const float* __restrict__ t, int nrows,
    const float* __restrict__ W2, const float* __restrict__ W3,
    const float* __restrict__ W4)
{
    __shared__ float s_lo[8], s_hi[8];
    int tid = threadIdx.x;

    // ---- edge reduce
    float l = 3.4e38f, h = -3.4e38f;
    for (int r = tid; r < nrows; r += 256) {
        l = fminf(l, t[(size_t)r * N_SEQ]);
        h = fmaxf(h, t[(size_t)r * N_SEQ + (N_SEQ - 1)]);
    }
    unsigned m = 0xffffffffu;
#pragma unroll
    for (int off = 16; off > 0; off >>= 1) {
        l = fminf(l, __shfl_down_sync(m, l, off));
        h = fmaxf(h, __shfl_down_sync(m, h, off));
    }
    int warp = tid >> 5, lane = tid & 31;
    if (lane == 0) { s_lo[warp] = l; s_hi[warp] = h; }

    // ---- pack weights (no sync needed with the reduce: independent data)
    const float4* W2v = reinterpret_cast<const float4*>(W2);
    const float4* W3v = reinterpret_cast<const float4*>(W3);
    const float4* W4v = reinterpret_cast<const float4*>(W4);
    for (int i = tid; i < 512; i += 256) {        // W2 [64 rows][8 float4]
        int k4 = i >> 6, j = i & 63;
        g_pW2[i] = W2v[j * 8 + k4];
    }
    for (int i = tid; i < 1024; i += 256) {       // W3 [64 rows][16 float4]
        int k4 = i >> 6, j = i & 63;
        g_pW3[i] = W3v[j * 16 + k4];
    }
    for (int i = tid; i < 512; i += 256) {        // W4 [32 rows][16 float4]
        int k4 = i >> 5, j = i & 31;
        g_pW4[i] = W4v[j * 16 + k4];
    }

    __syncthreads();
    if (tid == 0) {
        float lo = s_lo[0], hi = s_hi[0];
#pragma unroll
        for (int w = 1; w < 8; w++) {
            lo = fminf(lo, s_lo[w]);
            hi = fmaxf(hi, s_hi[w]);
        }
        float range = hi - lo;
        float hh = (range > 1e-30f) ? range * (1.0f / TBL_N) : 1.0f;
        float inv_h = (range > 1e-30f) ? (float)TBL_N / range : 0.0f;
        g_range = make_float2(lo, inv_h);
        g_h = hh;
    }
}

// -------------------------- kernel 1: f at knots (warp-per-knot) ------------
// No block-wide syncs; weights via __ldg from packed scratch (L1/L2-resident,
// coalesced float4 per warp). Hidden vectors in per-warp smem ping-pong.
__global__ __launch_bounds__(256) void table_kernel(
    const float* __restrict__ W1, const float* __restrict__ b1,
    const float* __restrict__ b2, const float* __restrict__ b3,
    const float* __restrict__ b4,
    const float* __restrict__ W5, const float* __restrict__ b5)
{
    __shared__ __align__(16) float hbuf[8][2][64];  // [warp][pingpong][unit]

    int tid  = threadIdx.x;
    int wid  = tid >> 5;
    int lane = tid & 31;
    int kn = blockIdx.x * 8 + wid;           // knot index for this warp
    if (kn > TBL_N) return;

    float2 rg = g_range;
    float tv = rg.x + (float)kn * g_h;
    const unsigned m = 0xffffffffu;

    // ---- layer 1: 1 -> 32
    hbuf[wid][0][lane] = splus(fmaf(tv, __ldg(&W1[lane]), __ldg(&b1[lane])));
    __syncwarp();

    // ---- layer 2: 32 -> 64 ; lane j handles units j, j+32
    {
        const float4* hv4 = reinterpret_cast<const float4*>(hbuf[wid][0]);
        float a0 = __ldg(&b2[lane]), a1 = __ldg(&b2[lane + 32]);
#pragma unroll
        for (int k4 = 0; k4 < 8; k4++) {
            float4 hv = hv4[k4];
            float4 w0 = __ldg(&g_pW2[k4 * 64 + lane]);
            float4 w1 = __ldg(&g_pW2[k4 * 64 + 32 + lane]);
            a0 = fmaf(w0.x, hv.x, a0); a0 = fmaf(w0.y, hv.y, a0);
            a0 = fmaf(w0.z, hv.z, a0); a0 = fmaf(w0.w, hv.w, a0);
            a1 = fmaf(w1.x, hv.x, a1); a1 = fmaf(w1.y, hv.y, a1);
            a1 = fmaf(w1.z, hv.z, a1); a1 = fmaf(w1.w, hv.w, a1);
        }
        hbuf[wid][1][lane]      = splus(a0);
        hbuf[wid][1][lane + 32] = splus(a1);
    }
    __syncwarp();

    // ---- layer 3: 64 -> 64
    {
        const float4* hv4 = reinterpret_cast<const float4*>(hbuf[wid][1]);
        float a0 = __ldg(&b3[lane]), a1 = __ldg(&b3[lane + 32]);
#pragma unroll
        for (int k4 = 0; k4 < 16; k4++) {
            float4 hv = hv4[k4];
            float4 w0 = __ldg(&g_pW3[k4 * 64 + lane]);
            float4 w1 = __ldg(&g_pW3[k4 * 64 + 32 + lane]);
            a0 = fmaf(w0.x, hv.x, a0); a0 = fmaf(w0.y, hv.y, a0);
            a0 = fmaf(w0.z, hv.z, a0); a0 = fmaf(w0.w, hv.w, a0);
            a1 = fmaf(w1.x, hv.x, a1); a1 = fmaf(w1.y, hv.y, a1);
            a1 = fmaf(w1.z, hv.z, a1); a1 = fmaf(w1.w, hv.w, a1);
        }
        hbuf[wid][0][lane]      = splus(a0);
        hbuf[wid][0][lane + 32] = splus(a1);
    }
    __syncwarp();

    // ---- layer 4: 64 -> 32 ; lane j = unit j
    float h4;
    {
        const float4* hv4 = reinterpret_cast<const float4*>(hbuf[wid][0]);
        float a0 = __ldg(&b4[lane]);
#pragma unroll
        for (int k4 = 0; k4 < 16; k4++) {
            float4 hv = hv4[k4];
            float4 w0 = __ldg(&g_pW4[k4 * 32 + lane]);
            a0 = fmaf(w0.x, hv.x, a0); a0 = fmaf(w0.y, hv.y, a0);
            a0 = fmaf(w0.z, hv.z, a0); a0 = fmaf(w0.w, hv.w, a0);
        }
        h4 = splus(a0);
    }

    // ---- layer 5: 32 -> 1 (warp reduce)
    float p = h4 * __ldg(&W5[lane]);
#pragma unroll
    for (int off = 16; off > 0; off >>= 1)
        p += __shfl_xor_sync(m, p, off);

    if (lane == 0) {
        float v = splus(p + __ldg(&b5[0])) + 1.0f;
        float* tbl = reinterpret_cast<float*>(g_tbl2);
        // slot kn: (f[kn], f[kn+1]); warp kn fills .x of kn and .y of kn-1.
        if (kn < TBL_N) tbl[2 * kn] = v;
        if (kn >= 1)    tbl[2 * (kn - 1) + 1] = v;
    }
}

// -------------------- kernel 2: antiderivative coefficients -----------------
// G(x) on interval i, frac = (x - x_i)/h in [0,1]:
//   G = G_i + a_i*frac + b_i*frac^2,  a_i = h*f_i,  b_i = 0.5*h*(f_{i+1}-f_i)
__global__ __launch_bounds__(512) void prefix_kernel()
{
    __shared__ float wsum[16];
    int tid = threadIdx.x;
    int lane = tid & 31, warp = tid >> 5;
    const unsigned m = 0xffffffffu;
    float h = g_h;

    int i0 = 2 * tid, i1 = 2 * tid + 1;
    float2 f0 = g_tbl2[i0];
    float2 f1 = g_tbl2[i1];
    float a0 = h * f0.x, b0 = 0.5f * h * (f0.y - f0.x);
    float a1 = h * f1.x, b1 = 0.5f * h * (f1.y - f1.x);
    float s0 = a0 + b0, s1 = a1 + b1;
    float tot = s0 + s1;

    float v = tot;
#pragma unroll
    for (int off = 1; off < 32; off <<= 1) {
        float n = __shfl_up_sync(m, v, off);
        if (lane >= off) v += n;
    }
    if (lane == 31) wsum[warp] = v;
    __syncthreads();
    if (warp == 0) {
        float w = (lane < 16) ? wsum[lane] : 0.0f;
#pragma unroll
        for (int off = 1; off < 16; off <<= 1) {
            float n = __shfl_up_sync(m, w, off);
            if (lane >= off) w += n;
        }
        if (lane < 16) wsum[lane] = w;
    }
    __syncthreads();

    float excl = ((warp > 0) ? wsum[warp - 1] : 0.0f) + (v - tot);
    g_coef[i0] = make_float4(excl,      a0, b0, 0.0f);
    g_coef[i1] = make_float4(excl + s0, a1, b1, 0.0f);
}

// -------------------------- kernel 3: pure map ------------------------------
#define S_THREADS 512
#define V4PT      (CHUNK / 4 / S_THREADS)  // 2 float4 per thread

__device__ __forceinline__ float evalG(float tv, float lo, float inv_h) {
    float u = (tv - lo) * inv_h;
    u = fminf(fmaxf(u, 0.0f), (float)TBL_N);
    int i = (int)u;
    if (i > TBL_N - 1) i = TBL_N - 1;
    float frac = u - (float)i;
    float4 c = __ldg(&g_coef[i]);
    return fmaf(frac, fmaf(frac, c.z, c.y), c.x);
}

__global__ __launch_bounds__(S_THREADS) void map_kernel(
    const float* __restrict__ t, float* __restrict__ out)
{
    int gid = blockIdx.x;
    int row = gid >> 2;                       // NCHUNK = 4
    size_t base = (size_t)row * N_SEQ + (size_t)(gid & (NCHUNK - 1)) * CHUNK;

    float2 rg = g_range;
    float lo = rg.x, inv_h = rg.y;

    // row anchor
    float G0 = evalG(__ldg(&t[(size_t)row * N_SEQ]), lo, inv_h);

    const float4* t4 = reinterpret_cast<const float4*>(t + base);
    float4* o4 = reinterpret_cast<float4*>(out + base);
    int tid = threadIdx.x;
#pragma unroll
    for (int w = 0; w < V4PT; w++) {
        int idx = tid + w * S_THREADS;
        float4 v = t4[idx];
        float4 o;
        o.x = evalG(v.x, lo, inv_h) - G0;
        o.y = evalG(v.y, lo, inv_h) - G0;
        o.z = evalG(v.z, lo, inv_h) - G0;
        o.w = evalG(v.w, lo, inv_h) - G0;
        o4[idx] = o;
    }
}

// ----------------------------------------------------------------------------
extern "C" void kernel_launch(void* const* d_in, const int* in_sizes, int n_in,
                              void* d_out, int out_size) {
    const float* t  = (const float*)d_in[0];
    const float* W1 = (const float*)d_in[1];
    const float* b1 = (const float*)d_in[2];
    const float* W2 = (const float*)d_in[3];
    const float* b2 = (const float*)d_in[4];
    const float* W3 = (const float*)d_in[5];
    const float* b3 = (const float*)d_in[6];
    const float* W4 = (const float*)d_in[7];
    const float* b4 = (const float*)d_in[8];
    const float* W5 = (const float*)d_in[9];
    const float* b5 = (const float*)d_in[10];
    float* out = (float*)d_out;

    int total = in_sizes[0];          // B * N
    int nrows = total / N_SEQ;        // B

    prep_kernel<<<1, 256>>>(t, nrows, W2, W3, W4);
    int tbl_blocks = (TBL_N + 1 + 7) / 8;      // 8 knots (warps) per block
    table_kernel<<<tbl_blocks, 256>>>(W1, b1, b2, b3, b4, W5, b5);
    prefix_kernel<<<1, 512>>>();
    map_kernel<<<total / CHUNK, S_THREADS>>>(t, out);
}